// round 2
// baseline (speedup 1.0000x reference)
#include <cuda_runtime.h>
#include <cuda_fp16.h>
#include <cstdint>
#include <cstddef>

// ---------------- problem constants ----------------
#define O_DIM 4096
#define I_DIM 4096
#define S_DIM 2048
#define M_TOT 8192            // B*S = 4*2048
#define GRP   128             // quant group size along K

// ---------------- GEMM tiling ----------------
#define BM 128
#define BN 128
#define BK 128                // int8 elements per stage = one scale group
#define STAGES 4
#define NKS (I_DIM / BK)      // 32 k-stages
#define A_STG (BM * BK)       // 16384 B
#define B_STG (BN * BK)       // 16384 B
#define STAGE_BYTES (A_STG + B_STG)          // 32768
#define SCALE_OFF (STAGES * STAGE_BYTES)     // 131072
#define SCALE_PITCH 129                      // padded floats per group row
#define SMEM_TOTAL (SCALE_OFF + 32 * SCALE_PITCH * 4)  // 147584

// ---------------- device scratch ----------------
__device__ int8_t g_W8[(size_t)O_DIM * I_DIM];   // w_int - zero, int8 [O][I]
__device__ int8_t g_X8[(size_t)M_TOT * I_DIM];   // quantized activations [M][I]

// ---------------- asm helpers ----------------
__device__ __forceinline__ uint32_t smem_u32(const void* p) {
    uint32_t a;
    asm("{ .reg .u64 t; cvta.to.shared.u64 t, %1; cvt.u32.u64 %0, t; }" : "=r"(a) : "l"(p));
    return a;
}
#define CP_ASYNC16(saddr, gptr) \
    asm volatile("cp.async.cg.shared.global [%0], [%1], 16;" :: "r"(saddr), "l"(gptr) : "memory")
#define CP_COMMIT() asm volatile("cp.async.commit_group;" ::: "memory")
#define CP_WAIT2()  asm volatile("cp.async.wait_group 2;" ::: "memory")

#define LDSM_X4(r0, r1, r2, r3, addr)                                              \
    asm volatile("ldmatrix.sync.aligned.m8n8.x4.shared.b16 {%0,%1,%2,%3}, [%4];"   \
                 : "=r"(r0), "=r"(r1), "=r"(r2), "=r"(r3) : "r"(addr))

#define MMA_S8(c, a, b0_, b1_)                                                     \
    asm volatile("mma.sync.aligned.m16n8k32.row.col.s32.s8.s8.s32 "                \
                 "{%0,%1,%2,%3}, {%4,%5,%6,%7}, {%8,%9}, {%0,%1,%2,%3};"           \
                 : "+r"((c)[0]), "+r"((c)[1]), "+r"((c)[2]), "+r"((c)[3])          \
                 : "r"((a)[0]), "r"((a)[1]), "r"((a)[2]), "r"((a)[3]),             \
                   "r"(b0_), "r"(b1_))

// ---------------- kernel 1: pack weights to int8 (w_int - zero) ----------------
__global__ void wpack_kernel(const int* __restrict__ qw, const int* __restrict__ wz) {
    int t = blockIdx.x * blockDim.x + threadIdx.x;   // O*2048/4 threads
    int o = t >> 9;
    int j = (t & 511) * 4;              // int32 index within row, 0..2044
    int g = j >> 6;                     // group = (2j)/128
    int z = __ldg(&wz[o * 32 + g]);
    int4 q = *reinterpret_cast<const int4*>(qw + (size_t)o * 2048 + j);
    int qs[4] = {q.x, q.y, q.z, q.w};
    uint32_t lo = 0, hi = 0;
#pragma unroll
    for (int r = 0; r < 2; r++) {
        lo |= (uint32_t)(uint8_t)((qs[r] & 15) - z) << (r * 16);
        lo |= (uint32_t)(uint8_t)(((qs[r] >> 4) & 15) - z) << (r * 16 + 8);
        hi |= (uint32_t)(uint8_t)((qs[r + 2] & 15) - z) << (r * 16);
        hi |= (uint32_t)(uint8_t)(((qs[r + 2] >> 4) & 15) - z) << (r * 16 + 8);
    }
    uint2 out;
    out.x = lo; out.y = hi;
    *reinterpret_cast<uint2*>(&g_W8[(size_t)o * I_DIM + j * 2]) = out;
}

// ---------------- kernel 2: quantize activations to int8 ----------------
__global__ void quant_kernel(const float* __restrict__ x, const float* __restrict__ as_) {
    int t = blockIdx.x * blockDim.x + threadIdx.x;   // M*4096/8 threads
    size_t e8 = (size_t)t * 8;
    int m = (int)(e8 >> 12);
    float s = __ldg(&as_[m & (S_DIM - 1)]);
    float4 v0 = *reinterpret_cast<const float4*>(x + e8);
    float4 v1 = *reinterpret_cast<const float4*>(x + e8 + 4);
    float vv[8] = {v0.x, v0.y, v0.z, v0.w, v1.x, v1.y, v1.z, v1.w};
    uint32_t lo = 0, hi = 0;
#pragma unroll
    for (int i = 0; i < 4; i++) {
        int n = (int)rintf(vv[i] / s);
        n = max(-127, min(127, n));
        lo |= ((uint32_t)(uint8_t)(int8_t)n) << (i * 8);
    }
#pragma unroll
    for (int i = 0; i < 4; i++) {
        int n = (int)rintf(vv[4 + i] / s);
        n = max(-127, min(127, n));
        hi |= ((uint32_t)(uint8_t)(int8_t)n) << (i * 8);
    }
    uint2 out; out.x = lo; out.y = hi;
    *reinterpret_cast<uint2*>(&g_X8[e8]) = out;
}

// ---------------- kernel 3: int8 GEMM with group-wise promotion ----------------
__global__ void __launch_bounds__(512, 1)
gemm_kernel(const float* __restrict__ ws,         // weight_scale [O][32]
            const float* __restrict__ act_scale,  // [2048]
            const float* __restrict__ bias,       // [4096]
            float* __restrict__ out) {            // [M][O]
    extern __shared__ char smem[];
    const uint32_t sbase = smem_u32(smem);
    float* sscale = reinterpret_cast<float*>(smem + SCALE_OFF);

    const int tid  = threadIdx.x;
    const int lane = tid & 31;
    const int wid  = tid >> 5;
    const int wm   = wid & 3;       // 4 warps along M
    const int wn   = wid >> 2;      // 4 warps along N
    const int n0   = blockIdx.x * BN;
    const int m0   = blockIdx.y * BM;

    // ---- preload per-column group scales: sscale[g*129 + nl] = ws[(n0+nl)*32+g]
#pragma unroll 2
    for (int i = tid; i < BN * 32; i += 512) {
        int nl = i >> 5, g = i & 31;
        sscale[g * SCALE_PITCH + nl] = __ldg(&ws[(size_t)(n0 + nl) * 32 + g]);
    }

    // ---- per-thread ldmatrix address precompute
    const int mi = lane >> 3;          // matrix index 0..3
    const int rr = lane & 7;
    const int c0 = mi >> 1;            // k-half chunk offset
    const int roff = (mi & 1) * 8;
    int rowA[2], rowB[2];
#pragma unroll
    for (int mb = 0; mb < 2; mb++) rowA[mb] = wm * 32 + mb * 16 + roff + rr;
#pragma unroll
    for (int nb = 0; nb < 2; nb++) rowB[nb] = wn * 32 + nb * 16 + roff + rr;

    // ---- accumulators
    int   ai[2][4][4];
    float af[2][4][4];
#pragma unroll
    for (int mb = 0; mb < 2; mb++)
#pragma unroll
        for (int bb = 0; bb < 4; bb++)
#pragma unroll
            for (int r = 0; r < 4; r++) { ai[mb][bb][r] = 0; af[mb][bb][r] = 0.f; }

    // ---- stage loader (cp.async, XOR-swizzled 16B chunks)
    auto load_stage = [&](int ks, int slot) {
        const uint32_t sA = sbase + slot * STAGE_BYTES;
        const uint32_t sB = sA + A_STG;
        const int8_t* gA = g_X8 + (size_t)m0 * I_DIM + ks * BK;
        const int8_t* gB = g_W8 + (size_t)n0 * I_DIM + ks * BK;
#pragma unroll
        for (int i = 0; i < 2; i++) {
            int idx = tid + i * 512;
            int row = idx >> 3, ch = idx & 7;
            uint32_t sw = (uint32_t)(row * 128 + ((ch ^ (row & 7)) << 4));
            CP_ASYNC16(sA + sw, gA + (size_t)row * I_DIM + ch * 16);
            CP_ASYNC16(sB + sw, gB + (size_t)row * I_DIM + ch * 16);
        }
    };

    // ---- prologue: fill 3 of 4 stages
    for (int s = 0; s < STAGES - 1; s++) { load_stage(s, s); CP_COMMIT(); }

    const int q2 = (lane & 3) * 2;

    for (int ks = 0; ks < NKS; ks++) {
        CP_WAIT2();
        __syncthreads();
        // issue next stage into the slot freed last iteration
        const int pre = ks + STAGES - 1;
        if (pre < NKS) load_stage(pre, pre & (STAGES - 1));
        CP_COMMIT();

        const uint32_t sA = sbase + (ks & (STAGES - 1)) * STAGE_BYTES;
        const uint32_t sB = sA + A_STG;

#pragma unroll
        for (int kk = 0; kk < 4; kk++) {
            uint32_t a[2][4], br[2][4];
#pragma unroll
            for (int mb = 0; mb < 2; mb++) {
                int row = rowA[mb];
                uint32_t ad = sA + row * 128 + (((((uint32_t)kk << 1) | c0) ^ (row & 7)) << 4);
                LDSM_X4(a[mb][0], a[mb][1], a[mb][2], a[mb][3], ad);
            }
#pragma unroll
            for (int nb = 0; nb < 2; nb++) {
                int row = rowB[nb];
                uint32_t bd = sB + row * 128 + (((((uint32_t)kk << 1) | c0) ^ (row & 7)) << 4);
                LDSM_X4(br[nb][0], br[nb][1], br[nb][2], br[nb][3], bd);
            }
            // br[nb] regs: r0 = (block nb*2+0, k lo), r1 = (block nb*2+1, k lo),
            //              r2 = (block nb*2+0, k hi), r3 = (block nb*2+1, k hi)
#pragma unroll
            for (int mb = 0; mb < 2; mb++) {
#pragma unroll
                for (int bb = 0; bb < 4; bb++) {
                    const int nb = bb >> 1, e = bb & 1;
                    MMA_S8(ai[mb][bb], a[mb], br[nb][e], br[nb][2 + e]);
                }
            }
        }

        // ---- promote this group's int32 sums into float accumulators
#pragma unroll
        for (int bb = 0; bb < 4; bb++) {
            const int nl = wn * 32 + bb * 8 + q2;
            const float s0 = sscale[ks * SCALE_PITCH + nl];
            const float s1 = sscale[ks * SCALE_PITCH + nl + 1];
#pragma unroll
            for (int mb = 0; mb < 2; mb++) {
                af[mb][bb][0] += s0 * (float)ai[mb][bb][0];
                af[mb][bb][1] += s1 * (float)ai[mb][bb][1];
                af[mb][bb][2] += s0 * (float)ai[mb][bb][2];
                af[mb][bb][3] += s1 * (float)ai[mb][bb][3];
                ai[mb][bb][0] = 0; ai[mb][bb][1] = 0;
                ai[mb][bb][2] = 0; ai[mb][bb][3] = 0;
            }
        }
    }

    // ---- epilogue: out = af * act_scale[m] + bias[n]
#pragma unroll
    for (int mb = 0; mb < 2; mb++) {
        const int r0 = m0 + wm * 32 + mb * 16 + (lane >> 2);
        const int r1 = r0 + 8;
        const float sa0 = __ldg(&act_scale[r0 & (S_DIM - 1)]);
        const float sa1 = __ldg(&act_scale[r1 & (S_DIM - 1)]);
#pragma unroll
        for (int bb = 0; bb < 4; bb++) {
            const int n = n0 + wn * 32 + bb * 8 + q2;
            const float2 bv = *reinterpret_cast<const float2*>(bias + n);
            float2 o0, o1;
            o0.x = af[mb][bb][0] * sa0 + bv.x;
            o0.y = af[mb][bb][1] * sa0 + bv.y;
            o1.x = af[mb][bb][2] * sa1 + bv.x;
            o1.y = af[mb][bb][3] * sa1 + bv.y;
            *reinterpret_cast<float2*>(out + (size_t)r0 * O_DIM + n) = o0;
            *reinterpret_cast<float2*>(out + (size_t)r1 * O_DIM + n) = o1;
        }
    }
}

// ---------------- host launcher ----------------
extern "C" void kernel_launch(void* const* d_in, const int* in_sizes, int n_in,
                              void* d_out, int out_size) {
    const float* x    = (const float*)d_in[0];
    const int*   qw   = (const int*)d_in[1];
    const float* as_  = (const float*)d_in[2];
    const float* ws   = (const float*)d_in[3];
    const int*   wz   = (const int*)d_in[4];
    const float* bias = (const float*)d_in[5];
    float* out = (float*)d_out;

    wpack_kernel<<<(O_DIM * 2048 / 4) / 256, 256>>>(qw, wz);
    quant_kernel<<<((size_t)M_TOT * I_DIM / 8) / 256, 256>>>(x, as_);

    static bool attr_set = false;
    if (!attr_set) {
        cudaFuncSetAttribute(gemm_kernel, cudaFuncAttributeMaxDynamicSharedMemorySize,
                             SMEM_TOTAL);
        attr_set = true;
    }
    gemm_kernel<<<dim3(O_DIM / BN, M_TOT / BM), 512, SMEM_TOTAL>>>(ws, as_, bias, out);
}